// round 7
// baseline (speedup 1.0000x reference)
#include <cuda_runtime.h>
#include <cstdint>

// CostVolumeLayer3D, B=2 C=64 D=32 H=64 W=64, R=2.
// out[b, ch(s,dsh), d, h, w] = (1/125) * sum_c x1[b,c,d,h,w] * x2[b,c,d-dsh,h-i_s,w-j_s]
//   s in [-4,4], dsh in [-2,2], (i_s,j_s) = (min(2,s+2), max(-2,s-2)),
//   ch = (5s+dsh) mod 125. Channels 23..102 are identically zero.
// In-CTA shift split: warps 0-3 compute s=-4..0 (single-column loads),
// warps 4-7 compute s=1..4 (row loads). One shared cp.async x2 stream.
// Thread = (w-pair) x (d-pair); 16 warps/SM.

typedef unsigned long long ull;
#define LD64(p) (*reinterpret_cast<const ull*>(p))

static __device__ __forceinline__ void cp16(uint32_t dst, const float* src, int vsz) {
    asm volatile("cp.async.cg.shared.global [%0], [%1], 16, %2;"
                 :: "r"(dst), "l"(src), "r"(vsz));
}
static __device__ __forceinline__ ull pk2(uint32_t lo, uint32_t hi) {
    ull r; asm("mov.b64 %0, {%1,%2};" : "=l"(r) : "r"(lo), "r"(hi)); return r;
}
static __device__ __forceinline__ void unpk(uint32_t& lo, uint32_t& hi, ull v) {
    asm("mov.b64 {%0,%1}, %2;" : "=r"(lo), "=r"(hi) : "l"(v));
}
static __device__ __forceinline__ void fma2(ull& acc, ull a, ull b) {
    asm("fma.rn.f32x2 %0, %1, %2, %0;" : "+l"(acc) : "l"(a), "l"(b));
}
static __device__ __forceinline__ ull mul2(ull a, ull b) {
    ull r; asm("mul.rn.f32x2 %0, %1, %2;" : "=l"(r) : "l"(a), "l"(b)); return r;
}

// Per-buffer smem (floats): x2 only, 6 planes * (8 rows * 72 cols) = 3456
// (13824 B); smem col = global_w + 4 (W halo cols 2,3,68,69). 3 buffers.
extern __shared__ float sm[];

__global__ void __launch_bounds__(256, 2)
cv3d_kernel(const float* __restrict__ x1, const float* __restrict__ x2,
            float* __restrict__ out)
{
    const int tid  = threadIdx.x;
    const int warp = tid >> 5;
    const int hl   = warp & 3;          // row 0..3 within tile
    const int grp  = warp >> 2;         // 0: s=-4..0 (col arm), 1: s=1..4 (row arm)
    const int w    = (tid & 31) * 2;    // even w; thread owns (w, w+1)
    const int h0   = blockIdx.x * 4;
    const int d0   = blockIdx.y * 2;
    const int b    = blockIdx.z;

    const float* x1b = x1 + (size_t)b * 8388608;
    const float* x2b = x2 + (size_t)b * 8388608;
    float* outb = out + (size_t)b * 16384000;
    const uint32_t smb = (uint32_t)__cvta_generic_to_shared(sm);

    // ---- cp.async geometry: 768 chunks = 3/thread. chunk q = tid + 256k:
    //      plane = (tid>>7) + 2k, row = (tid>>4)&7, cw = tid&15 ----
    const int crow = (tid >> 4) & 7, ccw = tid & 15, p0 = tid >> 7;
    const int ghl  = h0 - 2 + crow;
    const bool ghok = ((unsigned)ghl < 64u);
    const float* srow = x2b + (size_t)(ghok ? ghl : 0) * 64 + ccw * 4;
    const uint32_t cdst0 = smb + (uint32_t)(p0 * 576 + crow * 72 + 4 + ccw * 4) * 4u;
    int gdo[3], vz[3];
    #pragma unroll
    for (int k = 0; k < 3; ++k) {
        int gd = d0 - 2 + p0 + 2 * k;
        vz[k]  = (ghok && (unsigned)gd < 32u) ? 16 : 0;
        int gdc = gd < 0 ? 0 : (gd > 31 ? 31 : gd);
        gdo[k] = gdc * 4096;            // element offset within channel
    }

    // ---- prologue: prefetch channels 0 (buf0) and 1 (buf1) ----
    #pragma unroll
    for (int pr = 0; pr < 2; ++pr) {
        #pragma unroll
        for (int k = 0; k < 3; ++k)
            cp16(cdst0 + (uint32_t)k * 4608u + (uint32_t)pr * 13824u,
                 srow + (size_t)pr * 131072 + gdo[k], vz[k]);
        asm volatile("cp.async.commit_group;");
    }

    // ---- zero W-halo columns of all 3 buffers (image edge => always 0) ----
    if (tid < 144) {
        int buf = tid / 48, r = tid % 48, pl = r >> 3, row = r & 7;
        float* hp = sm + buf * 3456 + pl * 576 + row * 72;
        hp[2] = 0.f; hp[3] = 0.f; hp[68] = 0.f; hp[69] = 0.f;
    }

    // ---- zero never-written channels: grp0 -> 23..62, grp1 -> 63..102 ----
    {
        int wt = tid & 127;
        float* zb = outb + (size_t)(23 + grp * 40) * 131072
                         + (size_t)d0 * 4096 + (size_t)h0 * 64;
        int dd = (wt >> 6) & 1, row = (wt >> 4) & 3, cw = wt & 15;
        float* base = zb + dd * 4096 + row * 64 + cw * 4;
        const float4 z = make_float4(0.f, 0.f, 0.f, 0.f);
        #pragma unroll 4
        for (int ch = 0; ch < 40; ++ch)
            *reinterpret_cast<float4*>(base + (size_t)ch * 131072) = z;
    }

    // ---- x1 register stream (both groups load the same values; L1-served) ----
    const float* x1p = x1b + (size_t)d0 * 4096 + (size_t)(h0 + hl) * 64 + w;
    ull A0 = LD64(x1p), A1 = LD64(x1p + 4096);

    // ---- accumulators [d][dsh+2][v], v = shift index within group ----
    ull acc[2][5][5];                   // grp1 uses only v=0..3
    #pragma unroll
    for (int a = 0; a < 2; ++a)
        #pragma unroll
        for (int u = 0; u < 5; ++u)
            #pragma unroll
            for (int v = 0; v < 5; ++v) acc[a][u][v] = 0ull;

    int cb = 0, pb = 2;
    #pragma unroll 1
    for (int c = 0; c < 64; ++c) {
        if (c < 63) asm volatile("cp.async.wait_group 1;");
        else        asm volatile("cp.async.wait_group 0;");
        __syncthreads();

        ull N0 = 0, N1 = 0;
        if (c < 63) {
            const float* nx = x1p + (size_t)(c + 1) * 131072;
            N0 = LD64(nx); N1 = LD64(nx + 4096);
        }
        if (c < 62) {
            const uint32_t pbo = (uint32_t)pb * 13824u;
            const float* sc = srow + (size_t)(c + 2) * 131072;
            #pragma unroll
            for (int k = 0; k < 3; ++k)
                cp16(cdst0 + (uint32_t)k * 4608u + pbo, sc + gdo[k], vz[k]);
            asm volatile("cp.async.commit_group;");
        }

        const float* xw = sm + cb * 3456 + hl * 72 + (w + 4); // (row gh-2, col w)
        if (grp == 0) {
            // ---- col arm: s=-4..0, b at (gh-2+r, w+2), r = 4..0 ----
            #pragma unroll
            for (int p = 0; p < 6; ++p) {
                const float* pp = xw + p * 576;
                ull bb[5];
                bb[0] = LD64(pp + 290);     // s=-4: (gh+2, w+2)
                bb[1] = LD64(pp + 218);     // s=-3
                bb[2] = LD64(pp + 146);     // s=-2
                bb[3] = LD64(pp + 74);      // s=-1
                bb[4] = LD64(pp + 2);       // s= 0: (gh-2, w+2)
                if (p <= 4) {
                    #pragma unroll
                    for (int v = 0; v < 5; ++v) fma2(acc[0][4 - p][v], A0, bb[v]);
                }
                if (p >= 1) {
                    #pragma unroll
                    for (int v = 0; v < 5; ++v) fma2(acc[1][5 - p][v], A1, bb[v]);
                }
            }
        } else {
            // ---- row arm: s=1..4, b in row gh-2, cols w-2..w+2 ----
            #pragma unroll
            for (int p = 0; p < 6; ++p) {
                const float* pp = xw + p * 576;
                ull f0 = LD64(pp - 2);      // (gh-2, w-2..w-1)
                ull f2 = LD64(pp);          // (gh-2, w..w+1)
                uint32_t f4lo = *reinterpret_cast<const uint32_t*>(pp + 2); // w+2
                uint32_t f0lo, f0hi, f2lo, f2hi;
                unpk(f0lo, f0hi, f0); unpk(f2lo, f2hi, f2);
                ull bb[4];
                bb[0] = pk2(f2hi, f4lo);    // s=1: (gh-2, w+1..w+2)
                bb[1] = f2;                 // s=2
                bb[2] = pk2(f0hi, f2lo);    // s=3
                bb[3] = f0;                 // s=4
                if (p <= 4) {
                    #pragma unroll
                    for (int v = 0; v < 4; ++v) fma2(acc[0][4 - p][v], A0, bb[v]);
                }
                if (p >= 1) {
                    #pragma unroll
                    for (int v = 0; v < 4; ++v) fma2(acc[1][5 - p][v], A1, bb[v]);
                }
            }
        }

        A0 = N0; A1 = N1;
        cb = (cb == 2) ? 0 : cb + 1;
        pb = (pb == 2) ? 0 : pb + 1;
    }

    // ---- epilogue: scale by 1/125 and store ----
    const uint32_t invb = __float_as_uint(1.0f / 125.0f);
    const ull invv = pk2(invb, invb);
    float* ob = outb + (size_t)d0 * 4096 + (size_t)(h0 + hl) * 64 + w;
    if (grp == 0) {
        #pragma unroll
        for (int a = 0; a < 2; ++a)
            #pragma unroll
            for (int u = 0; u < 5; ++u)
                #pragma unroll
                for (int v = 0; v < 5; ++v) {
                    int s = v - 4;
                    int ch = ((5 * s + (u - 2)) % 125 + 125) % 125;
                    ull r = mul2(acc[a][u][v], invv);
                    *reinterpret_cast<ull*>(ob + (size_t)ch * 131072 + a * 4096) = r;
                }
    } else {
        #pragma unroll
        for (int a = 0; a < 2; ++a)
            #pragma unroll
            for (int u = 0; u < 5; ++u)
                #pragma unroll
                for (int v = 0; v < 4; ++v) {
                    int s = v + 1;
                    int ch = 5 * s + (u - 2);     // 3..22, all positive
                    ull r = mul2(acc[a][u][v], invv);
                    *reinterpret_cast<ull*>(ob + (size_t)ch * 131072 + a * 4096) = r;
                }
    }
}

extern "C" void kernel_launch(void* const* d_in, const int* in_sizes, int n_in,
                              void* d_out, int out_size) {
    const float* x1 = (const float*)d_in[0];
    const float* x2 = (const float*)d_in[1];
    float* out = (float*)d_out;
    cudaFuncSetAttribute(cv3d_kernel,
                         cudaFuncAttributeMaxDynamicSharedMemorySize, 41472);
    cv3d_kernel<<<dim3(16, 16, 2), 256, 41472>>>(x1, x2, out);
}

// round 8
// speedup vs baseline: 1.6573x; 1.6573x over previous
#include <cuda_runtime.h>
#include <cstdint>

// CostVolumeLayer3D, B=2 C=64 D=32 H=64 W=64, R=2.
// out[b, ch(s,dsh), d, h, w] = (1/125) * sum_c x1[b,c,d,h,w] * x2[b,c,d-dsh,h-i_s,w-j_s]
//   s in [-4,4], dsh in [-2,2], (i_s,j_s) = (min(2,s+2), max(-2,s-2)),
//   ch = (5s+dsh) mod 125. Channels 23..102 are identically zero.
// R2 structure (128-thr CTA, 4 h-rows, thread = w-pair x d-pair, 90 f32x2 acc)
// with a DEEP cp.async pipeline: 6 buffers, prefetch distance 5, wait_group 4.

typedef unsigned long long ull;
#define LD64(p) (*reinterpret_cast<const ull*>(p))

static __device__ __forceinline__ void cp16(uint32_t dst, const float* src, int vsz) {
    asm volatile("cp.async.cg.shared.global [%0], [%1], 16, %2;"
                 :: "r"(dst), "l"(src), "r"(vsz));
}
static __device__ __forceinline__ ull pk2(uint32_t lo, uint32_t hi) {
    ull r; asm("mov.b64 %0, {%1,%2};" : "=l"(r) : "r"(lo), "r"(hi)); return r;
}
static __device__ __forceinline__ void unpk(uint32_t& lo, uint32_t& hi, ull v) {
    asm("mov.b64 {%0,%1}, %2;" : "=r"(lo), "=r"(hi) : "l"(v));
}
static __device__ __forceinline__ void fma2(ull& acc, ull a, ull b) {
    asm("fma.rn.f32x2 %0, %1, %2, %0;" : "+l"(acc) : "l"(a), "l"(b));
}
static __device__ __forceinline__ ull mul2(ull a, ull b) {
    ull r; asm("mul.rn.f32x2 %0, %1, %2;" : "=l"(r) : "l"(a), "l"(b)); return r;
}

// Per-buffer smem layout (floats), 6 buffers (BUF = 3968 floats = 15872 B):
//   x2: 6 planes * (8 rows * 72 cols); smem col = global_w + 4 (W halo cols 2,3,68,69)
//   x1 at +3456: 2 planes * (4 rows * 64 cols)
extern __shared__ float sm[];

__global__ void __launch_bounds__(128, 2)
cv3d_kernel(const float* __restrict__ x1, const float* __restrict__ x2,
            float* __restrict__ out)
{
    const int tid = threadIdx.x;
    const int hl  = tid >> 5;           // 0..3: h row within tile (warp = one row)
    const int w   = (tid & 31) * 2;     // even w; thread owns (w, w+1)
    const int h0  = blockIdx.x * 4;
    const int d0  = blockIdx.y * 2;
    const int b   = blockIdx.z;

    const float* x1b = x1 + (size_t)b * 8388608;
    const float* x2b = x2 + (size_t)b * 8388608;
    const uint32_t smb = (uint32_t)__cvta_generic_to_shared(sm);

    // ---- cp.async chunk table (channel-invariant): 768 x2 + 128 x1 = 896 = 7*128 ----
    const float* csrc[7]; uint32_t cdst[7]; int cvsz[7];
    #pragma unroll
    for (int k = 0; k < 7; ++k) {
        int q = tid + k * 128;
        const float* s; uint32_t doff; int v;
        if (q < 768) {                        // x2: 6 planes, 8 rows, 16x16B chunks
            int pl = q >> 7, r = q & 127, row = r >> 4, cw = r & 15;
            int gd = d0 - 2 + pl, gh = h0 - 2 + row;
            bool inr = ((unsigned)gd < 32u) && ((unsigned)gh < 64u);
            v = inr ? 16 : 0;                 // src-size 0 => zero-fill (D/H halo)
            s = x2b + (size_t)(inr ? gd : 0) * 4096 + (inr ? gh : 0) * 64 + cw * 4;
            doff = (uint32_t)(pl * 576 + row * 72 + 4 + cw * 4);
        } else {                              // x1: 2 planes, 4 rows, 16x16B chunks
            int t = q - 768;
            int a = (t >> 6) & 1, row = (t >> 4) & 3, cw = t & 15;
            v = 16;
            s = x1b + (size_t)(d0 + a) * 4096 + (size_t)(h0 + row) * 64 + cw * 4;
            doff = (uint32_t)(3456 + a * 256 + row * 64 + cw * 4);
        }
        csrc[k] = s; cdst[k] = smb + doff * 4u; cvsz[k] = v;
    }

    // ---- prologue: prefetch channels 0..4 into buffers 0..4 ----
    #pragma unroll
    for (int pr = 0; pr < 5; ++pr) {
        #pragma unroll
        for (int k = 0; k < 7; ++k)
            cp16(cdst[k] + (uint32_t)pr * 15872u,
                 csrc[k] + (size_t)pr * 131072, cvsz[k]);
        asm volatile("cp.async.commit_group;");
    }

    // ---- zero W-halo columns of all 6 buffers (image edge => always 0) ----
    for (int q = tid; q < 288; q += 128) {
        int buf = q / 48, r = q % 48, pl = r >> 3, row = r & 7;
        float* hp = sm + buf * 3968 + pl * 576 + row * 72;
        hp[2] = 0.f; hp[3] = 0.f; hp[68] = 0.f; hp[69] = 0.f;
    }

    // ---- zero the 80 never-written output channels (23..102) for this tile ----
    {
        float* zb = out + (size_t)b * 16384000 + (size_t)23 * 131072
                        + (size_t)d0 * 4096 + (size_t)h0 * 64;
        int dd = (tid >> 6) & 1, row = (tid >> 4) & 3, cw = tid & 15;
        float* base = zb + dd * 4096 + row * 64 + cw * 4;
        const float4 z = make_float4(0.f, 0.f, 0.f, 0.f);
        #pragma unroll 4
        for (int ch = 0; ch < 80; ++ch)
            *reinterpret_cast<float4*>(base + (size_t)ch * 131072) = z;
    }

    // ---- accumulators: [d-index][dsh+2][s+4], f32x2 lanes = (w, w+1) ----
    ull acc[2][5][9];
    #pragma unroll
    for (int a = 0; a < 2; ++a)
        #pragma unroll
        for (int u = 0; u < 5; ++u)
            #pragma unroll
            for (int v = 0; v < 9; ++v) acc[a][u][v] = 0ull;

    int cb = 0;   // buffer holding channel c
    int pb = 5;   // buffer receiving channel c+5

    #pragma unroll 1
    for (int c = 0; c < 64; ++c) {
        // wait so that channel c's group is complete; tail steps the constant down
        if      (c < 60) asm volatile("cp.async.wait_group 4;");
        else if (c == 60) asm volatile("cp.async.wait_group 3;");
        else if (c == 61) asm volatile("cp.async.wait_group 2;");
        else if (c == 62) asm volatile("cp.async.wait_group 1;");
        else              asm volatile("cp.async.wait_group 0;");
        __syncthreads();

        if (c < 59) {
            const uint32_t pbo = (uint32_t)pb * 15872u;
            #pragma unroll
            for (int k = 0; k < 7; ++k)
                cp16(cdst[k] + pbo, csrc[k] + (size_t)(c + 5) * 131072, cvsz[k]);
            asm volatile("cp.async.commit_group;");
        }

        const float* base = sm + cb * 3968;
        const float* xw = base + hl * 72 + (w + 4);     // row (gh-2), col ww
        const float* ax = base + 3456 + hl * 64 + w;
        const ull A0 = LD64(ax);                        // x1 (d0,   gh, w..w+1)
        const ull A1 = LD64(ax + 256);                  // x1 (d0+1, gh, w..w+1)

        #pragma unroll
        for (int p = 0; p < 6; ++p) {                   // x2 plane gd = d0-2+p
            const float* pp = xw + p * 576;
            ull f0 = LD64(pp - 2);   // row gh-2: cols ww-2,ww-1
            ull f2 = LD64(pp);       //            cols ww,  ww+1
            ull f4 = LD64(pp + 2);   //            cols ww+2,ww+3
            ull l1 = LD64(pp + 74);  // row gh-1, cols ww+2,ww+3
            ull l2 = LD64(pp + 146); // row gh
            ull l3 = LD64(pp + 218); // row gh+1
            ull l4 = LD64(pp + 290); // row gh+2
            uint32_t f0lo, f0hi, f2lo, f2hi, f4lo, f4hi;
            unpk(f0lo, f0hi, f0); unpk(f2lo, f2hi, f2); unpk(f4lo, f4hi, f4);
            ull bb[9];
            bb[0] = l4;                 // s=-4
            bb[1] = l3;                 // s=-3
            bb[2] = l2;                 // s=-2
            bb[3] = l1;                 // s=-1
            bb[4] = f4;                 // s= 0
            bb[5] = pk2(f2hi, f4lo);    // s= 1
            bb[6] = f2;                 // s= 2
            bb[7] = pk2(f0hi, f2lo);    // s= 3
            bb[8] = f0;                 // s= 4
            if (p <= 4) {               // voxel d0:   u = 4-p
                #pragma unroll
                for (int v = 0; v < 9; ++v) fma2(acc[0][4 - p][v], A0, bb[v]);
            }
            if (p >= 1) {               // voxel d0+1: u = 5-p
                #pragma unroll
                for (int v = 0; v < 9; ++v) fma2(acc[1][5 - p][v], A1, bb[v]);
            }
        }

        cb = (cb == 5) ? 0 : cb + 1;
        pb = (pb == 5) ? 0 : pb + 1;
    }

    // ---- epilogue: scale by 1/125 and store ----
    const uint32_t invb = __float_as_uint(1.0f / 125.0f);
    const ull invv = pk2(invb, invb);
    float* ob = out + (size_t)b * 16384000 + (size_t)d0 * 4096
                    + (size_t)(h0 + hl) * 64 + w;
    #pragma unroll
    for (int a = 0; a < 2; ++a)
        #pragma unroll
        for (int u = 0; u < 5; ++u)
            #pragma unroll
            for (int v = 0; v < 9; ++v) {
                int ch = (5 * (v - 4) + (u - 2)) % 125;
                if (ch < 0) ch += 125;
                ull r = mul2(acc[a][u][v], invv);
                *reinterpret_cast<ull*>(ob + (size_t)ch * 131072 + a * 4096) = r;
            }
}

extern "C" void kernel_launch(void* const* d_in, const int* in_sizes, int n_in,
                              void* d_out, int out_size) {
    const float* x1 = (const float*)d_in[0];
    const float* x2 = (const float*)d_in[1];
    float* out = (float*)d_out;
    cudaFuncSetAttribute(cv3d_kernel,
                         cudaFuncAttributeMaxDynamicSharedMemorySize, 95232);
    cv3d_kernel<<<dim3(16, 16, 2), 128, 95232>>>(x1, x2, out);
}